// round 3
// baseline (speedup 1.0000x reference)
#include <cuda_runtime.h>
#include <math.h>

#define BB 16
#define CC 128
#define HH 128
#define WW 128
#define NP (HH*WW)          // 16384 spatial

// ---------------- scratch (device globals; no allocation allowed) ----------------
__device__ float g_t  [3ull*BB*CC*NP];   // conv1x1 outputs (pre-dwconv)   ~403 MB
__device__ float g_qkv[3ull*BB*CC*NP];   // q,k,v after dwconv             ~403 MB
__device__ float g_ss [2*BB*CC];         // sum of squares for q,k rows
__device__ float g_G  [BB*CC*CC];        // raw gram q.k^T
__device__ float g_A  [BB*CC*CC];        // softmax(normalized gram)
__device__ float g_M  [BB*CC*CC];        // aw @ A_b  (fused final weights)

// ---------------- zero the accumulators each launch ----------------
__global__ void k_zero()
{
    int i = blockIdx.x * blockDim.x + threadIdx.x;
    if (i < BB*CC*CC) g_G[i] = 0.0f;
    if (i < 2*BB*CC)  g_ss[i] = 0.0f;
}

// ---------------- 128x128 output tile SGEMM core, K=128 ----------------
// Out[r][n0+c] = sum_k W[r*128+k] * X[k*ldx + n0 + c]  (+ bias[r])
// 256 threads, 8x8 per-thread register tile, k-step 8.
__device__ __forceinline__ void gemm128_core(
    const float* __restrict__ Wp,       // [128,128] row-major
    const float* __restrict__ Xp,       // rows k, row stride ldx
    int ldx,
    float* __restrict__ Op, int ldo,
    const float* __restrict__ bias,     // may be null
    int n0)
{
    __shared__ float As[8][128];
    __shared__ float Bs[8][128];

    const int tid = threadIdx.x;
    const int tx  = tid & 15;
    const int ty  = tid >> 4;

    const int arow = tid >> 1;          // 0..127
    const int ak0  = (tid & 1) * 4;     // 0 or 4
    const int brow = tid >> 5;          // 0..7
    const int bcol = (tid & 31) * 4;    // 0..124

    float acc[8][8];
#pragma unroll
    for (int i = 0; i < 8; i++)
#pragma unroll
        for (int j = 0; j < 8; j++) acc[i][j] = 0.0f;

#pragma unroll 1
    for (int k0 = 0; k0 < 128; k0 += 8) {
        float4 wa = *(const float4*)(Wp + arow*128 + k0 + ak0);
        float4 xb = *(const float4*)(Xp + (size_t)(k0 + brow)*ldx + n0 + bcol);
        __syncthreads();
        As[ak0+0][arow] = wa.x;
        As[ak0+1][arow] = wa.y;
        As[ak0+2][arow] = wa.z;
        As[ak0+3][arow] = wa.w;
        *(float4*)(&Bs[brow][bcol]) = xb;
        __syncthreads();
#pragma unroll
        for (int kk = 0; kk < 8; kk++) {
            float4 a0 = *(const float4*)&As[kk][ty*4];
            float4 a1 = *(const float4*)&As[kk][64 + ty*4];
            float4 b0 = *(const float4*)&Bs[kk][tx*4];
            float4 b1 = *(const float4*)&Bs[kk][64 + tx*4];
            float a[8] = {a0.x,a0.y,a0.z,a0.w,a1.x,a1.y,a1.z,a1.w};
            float b[8] = {b0.x,b0.y,b0.z,b0.w,b1.x,b1.y,b1.z,b1.w};
#pragma unroll
            for (int i = 0; i < 8; i++)
#pragma unroll
                for (int j = 0; j < 8; j++)
                    acc[i][j] += a[i] * b[j];
        }
    }

#pragma unroll
    for (int i = 0; i < 8; i++) {
        int r = (i < 4) ? (ty*4 + i) : (64 + ty*4 + i - 4);
        float bv = bias ? bias[r] : 0.0f;
        float4 v0 = make_float4(acc[i][0]+bv, acc[i][1]+bv, acc[i][2]+bv, acc[i][3]+bv);
        float4 v1 = make_float4(acc[i][4]+bv, acc[i][5]+bv, acc[i][6]+bv, acc[i][7]+bv);
        *(float4*)(Op + (size_t)r*ldo + n0 + tx*4)      = v0;
        *(float4*)(Op + (size_t)r*ldo + n0 + 64 + tx*4) = v1;
    }
}

// ---------------- K1: fused q/k/v conv1x1 ----------------
__global__ void __launch_bounds__(256) k_conv1x1_qkv(
    const float* __restrict__ x,
    const float* __restrict__ qw, const float* __restrict__ qb,
    const float* __restrict__ kw, const float* __restrict__ kb,
    const float* __restrict__ vw, const float* __restrict__ vb)
{
    int b  = blockIdx.z;
    int j  = blockIdx.y;              // 0=q 1=k 2=v
    int n0 = blockIdx.x * 128;
    const float* W  = (j == 0) ? qw : (j == 1) ? kw : vw;
    const float* bi = (j == 0) ? qb : (j == 1) ? kb : vb;
    const float* X  = x + (size_t)b * CC * NP;
    float*       O  = g_t + ((size_t)j * BB + b) * CC * NP;
    gemm128_core(W, X, NP, O, NP, bi, n0);
}

// ---------------- K2: depthwise 3x3 (pad 1) + bias + sumsq for q,k ----------------
// grid: (4 strips, 128 channels, 48 = j*16+b), 256 threads
__global__ void __launch_bounds__(256) k_dwconv(
    const float* __restrict__ qdw, const float* __restrict__ qdb,
    const float* __restrict__ kdw, const float* __restrict__ kdb,
    const float* __restrict__ vdw, const float* __restrict__ vdb)
{
    int zz = blockIdx.z;
    int j = zz / BB, b = zz % BB;
    int c = blockIdx.y;
    int strip = blockIdx.x;           // 32-row strips
    const float* wsrc = ((j == 0) ? qdw : (j == 1) ? kdw : vdw) + c * 9;
    float bias = ((j == 0) ? qdb : (j == 1) ? kdb : vdb)[c];
    const float* in  = g_t   + (((size_t)j * BB + b) * CC + c) * NP;
    float*       out = g_qkv + (((size_t)j * BB + b) * CC + c) * NP;

    __shared__ float s[34][130];
    float w9[9];
#pragma unroll
    for (int i = 0; i < 9; i++) w9[i] = wsrc[i];

    const int r0  = strip * 32;
    const int tid = threadIdx.x;

    for (int idx = tid; idx < 34 * 130; idx += 256) {
        int pr = idx / 130, pc = idx % 130;
        int gy = r0 + pr - 1, gx = pc - 1;
        float v = 0.0f;
        if (gy >= 0 && gy < HH && gx >= 0 && gx < WW) v = in[gy * WW + gx];
        s[pr][pc] = v;
    }
    __syncthreads();

    float ssq = 0.0f;
#pragma unroll
    for (int it = 0; it < 16; it++) {
        int px  = tid + it * 256;
        int r   = px >> 7;
        int col = px & 127;
        float acc = bias;
#pragma unroll
        for (int ky = 0; ky < 3; ky++)
#pragma unroll
            for (int kx = 0; kx < 3; kx++)
                acc += w9[ky * 3 + kx] * s[r + ky][col + kx];
        out[(r0 + r) * WW + col] = acc;
        ssq += acc * acc;
    }
    if (j < 2) {
#pragma unroll
        for (int o = 16; o; o >>= 1) ssq += __shfl_down_sync(0xffffffffu, ssq, o);
        if ((tid & 31) == 0) atomicAdd(&g_ss[j * BB * CC + b * CC + c], ssq);
    }
}

// ---------------- K3: gram G[b][i][j] = sum_n q[i][n]*k[j][n], split-K atomics ----------------
// grid: (32 slices of 512, 1, 16 batches)
__global__ void __launch_bounds__(256) k_gram()
{
    int b = blockIdx.z;
    int nbase = blockIdx.x * 512;
    const float* q  = g_qkv + ((size_t)0 * BB + b) * CC * NP;
    const float* km = g_qkv + ((size_t)1 * BB + b) * CC * NP;

    __shared__ float As[8][128];
    __shared__ float Bs[8][128];
    const int tid = threadIdx.x;
    const int tx  = tid & 15;
    const int ty  = tid >> 4;
    const int row = tid >> 1;
    const int c0  = (tid & 1) * 4;

    float acc[8][8];
#pragma unroll
    for (int i = 0; i < 8; i++)
#pragma unroll
        for (int j = 0; j < 8; j++) acc[i][j] = 0.0f;

#pragma unroll 1
    for (int kk0 = 0; kk0 < 512; kk0 += 8) {
        float4 qa = *(const float4*)(q  + (size_t)row * NP + nbase + kk0 + c0);
        float4 ka = *(const float4*)(km + (size_t)row * NP + nbase + kk0 + c0);
        __syncthreads();
        As[c0+0][row] = qa.x; As[c0+1][row] = qa.y; As[c0+2][row] = qa.z; As[c0+3][row] = qa.w;
        Bs[c0+0][row] = ka.x; Bs[c0+1][row] = ka.y; Bs[c0+2][row] = ka.z; Bs[c0+3][row] = ka.w;
        __syncthreads();
#pragma unroll
        for (int kk = 0; kk < 8; kk++) {
            float4 a0 = *(const float4*)&As[kk][ty*4];
            float4 a1 = *(const float4*)&As[kk][64 + ty*4];
            float4 b0 = *(const float4*)&Bs[kk][tx*4];
            float4 b1 = *(const float4*)&Bs[kk][64 + tx*4];
            float a[8] = {a0.x,a0.y,a0.z,a0.w,a1.x,a1.y,a1.z,a1.w};
            float bv[8] = {b0.x,b0.y,b0.z,b0.w,b1.x,b1.y,b1.z,b1.w};
#pragma unroll
            for (int i = 0; i < 8; i++)
#pragma unroll
                for (int j = 0; j < 8; j++)
                    acc[i][j] += a[i] * bv[j];
        }
    }

    float* G = g_G + (size_t)b * CC * CC;
#pragma unroll
    for (int i = 0; i < 8; i++) {
        int r = (i < 4) ? (ty*4 + i) : (64 + ty*4 + i - 4);
#pragma unroll
        for (int j = 0; j < 8; j++) {
            int cc = (j < 4) ? (tx*4 + j) : (64 + tx*4 + j - 4);
            atomicAdd(&G[r * CC + cc], acc[i][j]);
        }
    }
}

// ---------------- K4: fold L2 norms + row softmax -> A ----------------
// grid (128 rows, 16 batches), 128 threads
__global__ void __launch_bounds__(128) k_softmax()
{
    int b = blockIdx.y, i = blockIdx.x;
    int t = threadIdx.x;

    float rq = 1.0f / fmaxf(sqrtf(g_ss[b * CC + i]), 1e-12f);
    float rk = 1.0f / fmaxf(sqrtf(g_ss[BB * CC + b * CC + t]), 1e-12f);
    size_t idx = (size_t)b * CC * CC + (size_t)i * CC + t;
    float val = g_G[idx] * rq * rk;

    __shared__ float redm[4];
    __shared__ float reds[4];

    float m = val;
#pragma unroll
    for (int o = 16; o; o >>= 1) m = fmaxf(m, __shfl_xor_sync(0xffffffffu, m, o));
    if ((t & 31) == 0) redm[t >> 5] = m;
    __syncthreads();
    m = fmaxf(fmaxf(redm[0], redm[1]), fmaxf(redm[2], redm[3]));

    float e = expf(val - m);
    float ssum = e;
#pragma unroll
    for (int o = 16; o; o >>= 1) ssum += __shfl_xor_sync(0xffffffffu, ssum, o);
    if ((t & 31) == 0) reds[t >> 5] = ssum;
    __syncthreads();
    float tot = reds[0] + reds[1] + reds[2] + reds[3];

    g_A[idx] = e / tot;
}

// ---------------- K5: M_b = aw @ A_b  (tiny per-batch GEMM) ----------------
__global__ void __launch_bounds__(256) k_makeM(const float* __restrict__ aw)
{
    int b = blockIdx.z;
    gemm128_core(aw, g_A + (size_t)b * CC * CC, CC,
                 g_M + (size_t)b * CC * CC, CC, nullptr, 0);
}

// ---------------- K6: out = M_b @ v_b + ab  (fused attention-apply + final conv1x1) ----------------
__global__ void __launch_bounds__(256) k_final(const float* __restrict__ ab, float* __restrict__ out)
{
    int b  = blockIdx.z;
    int n0 = blockIdx.x * 128;
    const float* Wp = g_M + (size_t)b * CC * CC;
    const float* V  = g_qkv + ((size_t)2 * BB + b) * CC * NP;
    gemm128_core(Wp, V, NP, out + (size_t)b * CC * NP, NP, ab, n0);
}

// ---------------- launch ----------------
extern "C" void kernel_launch(void* const* d_in, const int* in_sizes, int n_in,
                              void* d_out, int out_size)
{
    const float* x   = (const float*)d_in[0];
    const float* qw  = (const float*)d_in[1];
    const float* qb  = (const float*)d_in[2];
    const float* qdw = (const float*)d_in[3];
    const float* qdb = (const float*)d_in[4];
    const float* kw  = (const float*)d_in[5];
    const float* kb  = (const float*)d_in[6];
    const float* kdw = (const float*)d_in[7];
    const float* kdb = (const float*)d_in[8];
    const float* vw  = (const float*)d_in[9];
    const float* vb  = (const float*)d_in[10];
    const float* vdw = (const float*)d_in[11];
    const float* vdb = (const float*)d_in[12];
    const float* aw  = (const float*)d_in[13];
    const float* ab  = (const float*)d_in[14];
    float* out = (float*)d_out;

    k_zero<<<(BB*CC*CC + 255) / 256, 256>>>();
    k_conv1x1_qkv<<<dim3(NP/128, 3, BB), 256>>>(x, qw, qb, kw, kb, vw, vb);
    k_dwconv<<<dim3(4, CC, 3*BB), 256>>>(qdw, qdb, kdw, kdb, vdw, vdb);
    k_gram<<<dim3(32, 1, BB), 256>>>();
    k_softmax<<<dim3(CC, BB), 128>>>();
    k_makeM<<<dim3(1, 1, BB), 256>>>(aw);
    k_final<<<dim3(NP/128, 1, BB), 256>>>(ab, out);
}